// round 14
// baseline (speedup 1.0000x reference)
#include <cuda_runtime.h>
#include <math.h>

// ----------------------------------------------------------------------------
// SINGLE-KERNEL exact binned solution. B=8192, labels in {0,1}.
//   equal-label pairs: relu(m) each -> closed form from n1
//   mixed pairs:       relu((m + p_neg) - p_pos)
// Phase 1 (all 32 blocks): BCE partials + scatter BOTH classes into 1024 bins
//   (count, sum, value list per bin; spill -> overflow lists, never in practice).
// Phase 2 (last-finishing block only):
//   suffix scan of neg bins ->
//   per-bin closed form  cntPos_b*sufS(b+1) - sumPos_b*sufC(b+1)   (no gather)
//   + per-bin dense cross posList_b x negList_b (~4x4 typical)
//   + exact overflow paths + BCE finalize + outputs + state reset.
// ----------------------------------------------------------------------------

#define TB    256
#define GBMAX 64
#define MAXB  8192
#define NBIN  1024
#define BPT   4                 // consecutive bins per thread in the scan
#define NK    4                 // interleaved bins per thread in the work pass
#define CAP   48
#define BLO   (-6.0f)
#define BHI   (7.0f)
#define INVW  ((float)NBIN / (BHI - BLO))

// scratch (allocation-free rule: __device__ globals)
__device__ int      g_nc[NBIN];            // neg attempt counts
__device__ float    g_ns[NBIN];            // neg stored sums (c = m + pred)
__device__ int      g_pc[NBIN];            // pos attempt counts
__device__ float    g_ps[NBIN];            // pos stored sums
__device__ float    g_nbins[NBIN * CAP];   // stored neg c values
__device__ float    g_pbins[NBIN * CAP];   // stored pos values
__device__ float    g_ovfN[MAXB];
__device__ float    g_ovfP[MAXB];
__device__ int      g_novf = 0;
__device__ int      g_povf = 0;
__device__ double   g_bceB[GBMAX];
__device__ unsigned g_done = 0;

__device__ __forceinline__ float read_margin(const void* p) {
    if (p == nullptr) return 1.0f;
    int v = *(const int*)p;
    if (v >= -1000000 && v <= 1000000) return (float)v;   // int scalar
    return __int_as_float(v);                             // float bits
}

__device__ __forceinline__ int bin_of(float x) {
    int b = (int)floorf((x - BLO) * INVW);
    return max(0, min(NBIN - 1, b));
}

__global__ void __launch_bounds__(TB)
fused(const float* __restrict__ preds,  const float* __restrict__ labels,
      const float* __restrict__ logits, const float* __restrict__ targets,
      const float* __restrict__ pw_, int n, const void* __restrict__ marginp,
      float* __restrict__ out)
{
    const int tid  = threadIdx.x;
    const int lane = tid & 31, w = tid >> 5;
    const int i    = blockIdx.x * TB + tid;
    const float m  = read_margin(marginp);
    const float pw = pw_[0];

    // ======================= Phase 1: scatter + BCE ========================
    float bce = 0.f;
    if (i < n) {
        const float p  = preds[i];
        const bool  fl = (labels[i] > 0.5f);
        const float x  = logits[i];
        const float t  = targets[i];
        const float mv = fmaxf(-x, 0.0f);
        const float sp = __logf(__expf(-mv) + __expf(-x - mv)) + mv;
        bce = (1.0f - t) * x + (1.0f + (pw - 1.0f) * t) * sp;

        if (fl) {                                  // positive
            const int  b   = bin_of(p);
            const int  idx = atomicAdd(&g_pc[b], 1);
            if (idx < CAP) {
                g_pbins[b * CAP + idx] = p;
                atomicAdd(&g_ps[b], p);
            } else {
                const int oi = atomicAdd(&g_povf, 1);
                if (oi < MAXB) g_ovfP[oi] = p;
            }
        } else {                                   // negative -> c = m + p
            const float c   = m + p;
            const int   b   = bin_of(c);
            const int   idx = atomicAdd(&g_nc[b], 1);
            if (idx < CAP) {
                g_nbins[b * CAP + idx] = c;
                atomicAdd(&g_ns[b], c);
            } else {
                const int oi = atomicAdd(&g_novf, 1);
                if (oi < MAXB) g_ovfN[oi] = c;
            }
        }
    }

    // BCE block reduce -> one store per block
    double d = (double)bce;
    #pragma unroll
    for (int off = 16; off; off >>= 1)
        d += __shfl_down_sync(0xffffffffu, d, off);
    __shared__ double wb8[8];
    if (lane == 0) wb8[w] = d;
    __syncthreads();
    if (tid == 0) {
        double s = 0.0;
        #pragma unroll
        for (int k = 0; k < 8; k++) s += wb8[k];
        g_bceB[blockIdx.x] = s;
    }

    __threadfence();
    __shared__ int isLast;
    if (tid == 0)
        isLast = (atomicAdd(&g_done, 1u) == gridDim.x - 1u) ? 1 : 0;
    __syncthreads();
    if (!isLast) return;

    // =============== Phase 2 (last block only): bin algebra ================
    __shared__ double ssufS[NBIN + 1];      // suffix of stored-neg sums
    __shared__ int    ssufC[NBIN + 1];      // suffix of stored-neg counts

    // suffix scan: thread owns consecutive bins [BPT*tid, BPT*tid+BPT)
    double v[BPT]; int c4[BPT]; int rawp = 0;
    #pragma unroll
    for (int k = 0; k < BPT; k++) {
        const int b = BPT * tid + k;
        c4[k]  = min(__ldcg(&g_nc[b]), CAP);
        v[k]   = (double)__ldcg(&g_ns[b]);
        rawp  += __ldcg(&g_pc[b]);          // raw attempts = true pos count
    }
    double Tt = 0.0; int Ct = 0;
    #pragma unroll
    for (int k = 0; k < BPT; k++) { Tt += v[k]; Ct += c4[k]; }

    __shared__ double tS[TB];
    __shared__ int    tC[TB];
    tS[tid] = Tt; tC[tid] = Ct;
    __syncthreads();
    for (int off = 1; off < TB; off <<= 1) {
        double aS = 0.0; int aC = 0;
        if (tid + off < TB) { aS = tS[tid + off]; aC = tC[tid + off]; }
        __syncthreads();
        tS[tid] += aS; tC[tid] += aC;
        __syncthreads();
    }
    double accS = tS[tid] - Tt;             // suffix strictly after my bins
    int    accC = tC[tid] - Ct;
    #pragma unroll
    for (int k = BPT - 1; k >= 0; k--) {
        const int b = BPT * tid + k;
        ssufS[b + 1] = accS;                // suffix starting at bin b+1
        ssufC[b + 1] = accC;
        accS += v[k]; accC += c4[k];
    }
    __syncthreads();                        // (index 0 never read)

    // balanced per-bin work: interleaved assignment b = tid + 256*k
    double acc = 0.0;
    #pragma unroll
    for (int k = 0; k < NK; k++) {
        const int b  = tid + TB * k;
        const int cp = min(__ldcg(&g_pc[b]), CAP);
        if (cp == 0) continue;
        const float sp = __ldcg(&g_ps[b]);
        // all stored negs in strictly-higher bins (c >= a guaranteed)
        acc += (double)cp * ssufS[b + 1] - (double)sp * (double)ssufC[b + 1];
        // same-bin dense cross (stored lists)
        const int cn = min(__ldcg(&g_nc[b]), CAP);
        if (cn) {
            const float* np = &g_nbins[b * CAP];
            const float* pp = &g_pbins[b * CAP];
            float s = 0.f;
            for (int ii = 0; ii < cp; ii++) {
                const float a = pp[ii];
                float t0 = 0.f;
                for (int j = 0; j < cn; j++)
                    t0 += fmaxf(np[j] - a, 0.f);
                s += t0;
            }
            acc += (double)s;
        }
    }

    // overflow paths (exact, disjoint; never taken for CAP=48 in practice)
    const int novf = min(__ldcg(&g_novf), MAXB);
    const int povf = min(__ldcg(&g_povf), MAXB);
    if (novf) {                              // ovf-neg x ALL pos (raw scan)
        for (int t = tid; t < novf; t += TB) {
            const float c = g_ovfN[t];
            float s = 0.f;
            for (int j = 0; j < n; j++)
                if (labels[j] > 0.5f) s += fmaxf(c - preds[j], 0.f);
            acc += (double)s;
        }
    }
    if (povf) {                              // ovf-pos x stored negs only
        for (int t = tid; t < povf; t += TB) {
            const float a = g_ovfP[t];
            const int   b = bin_of(a);
            acc += ssufS[b + 1] - (double)a * (double)ssufC[b + 1];
            const int cn = min(__ldcg(&g_nc[b]), CAP);
            float s = 0.f;
            for (int j = 0; j < cn; j++)
                s += fmaxf(g_nbins[b * CAP + j] - a, 0.f);
            acc += (double)s;
        }
    }

    // BCE partials of all blocks
    double fb = 0.0;
    for (int j = tid; j < (int)gridDim.x; j += TB) fb += __ldcg(&g_bceB[j]);

    // final block reduce: acc (fp64), fb (fp64), rawp (int)
    #pragma unroll
    for (int off = 16; off; off >>= 1) {
        acc  += __shfl_down_sync(0xffffffffu, acc,  off);
        fb   += __shfl_down_sync(0xffffffffu, fb,   off);
        rawp += __shfl_down_sync(0xffffffffu, rawp, off);
    }
    __shared__ double zm[8], zb[8];
    __shared__ int    zp[8];
    if (lane == 0) { zm[w] = acc; zb[w] = fb; zp[w] = rawp; }
    __syncthreads();
    if (tid == 0) {
        double sm = 0.0, sb = 0.0; int n1 = 0;
        #pragma unroll
        for (int k = 0; k < 8; k++) { sm += zm[k]; sb += zb[k]; n1 += zp[k]; }
        const double dn1 = (double)n1, dn0 = (double)(n - n1);
        const double eqPairs = 0.5 * (dn1 * (dn1 - 1.0) + dn0 * (dn0 - 1.0));
        const double mm = (m > 0.0f) ? (double)m : 0.0;
        out[0] = (float)((mm * eqPairs + sm) / (double)n);
        out[1] = (float)(sb / (double)n);
    }
    __syncthreads();
    // reset persistent state for next graph replay
    for (int j = tid; j < NBIN; j += TB) {
        g_nc[j] = 0; g_ns[j] = 0.f;
        g_pc[j] = 0; g_ps[j] = 0.f;
    }
    if (tid == 0) { g_novf = 0; g_povf = 0; g_done = 0u; }
}

// ---------------------------------------------------------------------------
extern "C" void kernel_launch(void* const* d_in, const int* in_sizes, int n_in,
                              void* d_out, int out_size)
{
    const float* preds   = (const float*)d_in[0];
    const float* labels  = (const float*)d_in[1];
    const float* logits  = (const float*)d_in[2];
    const float* targets = (const float*)d_in[3];
    const float* pw      = (const float*)d_in[4];
    const void*  marginp = (n_in >= 6) ? d_in[5] : nullptr;
    const int n = in_sizes[0];
    float* out = (float*)d_out;

    const int g = min((n + TB - 1) / TB, GBMAX);   // 32 for B=8192
    fused<<<g, TB>>>(preds, labels, logits, targets, pw, n, marginp, out);
}

// round 15
// speedup vs baseline: 1.2754x; 1.2754x over previous
#include <cuda_runtime.h>
#include <math.h>

// ----------------------------------------------------------------------------
// Exact binned solution, all heavy steps parallel. B=8192, labels in {0,1}.
//   equal-label pairs: relu(m) each -> closed form from n1
//   mixed pairs:       relu((m + p_neg) - p_pos)
// k1: BCE partials + scatter both classes into 1024 bins (count/sum/list).
// k2: EVERY block builds the neg-bin suffix arrays in smem (redundant but
//     parallel); per-pos closed form via LDS; same-bin dense crosses spread
//     one-bin-per-(block,thread); last block: tiny reduce + outputs + reset.
// Overflow lists keep it exact for any input (never taken at CAP=48).
// ----------------------------------------------------------------------------

#define T1    256
#define T2    256
#define GMAX  64
#define MAXB  8192
#define NBIN  1024
#define BPT   4                 // bins per thread in the scan (NBIN / T2)
#define CAP   48
#define BLO   (-6.0f)
#define BHI   (7.0f)
#define INVW  ((float)NBIN / (BHI - BLO))

// scratch (allocation-free rule: __device__ globals)
__device__ int      g_nc[NBIN];            // neg attempt counts
__device__ float    g_ns[NBIN];            // neg stored sums (c = m + pred)
__device__ int      g_pc[NBIN];            // pos attempt counts
__device__ float    g_ps[NBIN];            // pos stored sums
__device__ float    g_nbins[NBIN * CAP];   // stored neg c values
__device__ float    g_pbins[NBIN * CAP];   // stored pos values
__device__ float    g_ovfN[MAXB];
__device__ float    g_ovfP[MAXB];
__device__ int      g_novf = 0;
__device__ int      g_povf = 0;
__device__ int      g_n1   = 0;
__device__ double   g_bceB[GMAX];
__device__ double   g_mixB[GMAX];
__device__ unsigned g_done2 = 0;

__device__ __forceinline__ float read_margin(const void* p) {
    if (p == nullptr) return 1.0f;
    int v = *(const int*)p;
    if (v >= -1000000 && v <= 1000000) return (float)v;   // int scalar
    return __int_as_float(v);                             // float bits
}

__device__ __forceinline__ int bin_of(float x) {
    int b = (int)floorf((x - BLO) * INVW);
    return max(0, min(NBIN - 1, b));
}

// ---------------------------------------------------------------------------
// Kernel 1: BCE partials + n1 + binned scatter. No tail work.
// ---------------------------------------------------------------------------
__global__ void __launch_bounds__(T1)
k1(const float* __restrict__ preds,  const float* __restrict__ labels,
   const float* __restrict__ logits, const float* __restrict__ targets,
   const float* __restrict__ pw_, int n, const void* __restrict__ marginp)
{
    const int tid  = threadIdx.x;
    const int lane = tid & 31, w = tid >> 5;
    const int i    = blockIdx.x * T1 + tid;
    const float m  = read_margin(marginp);
    const float pw = pw_[0];

    float bce = 0.f;
    bool pos = false;
    if (i < n) {
        const float p  = preds[i];
        pos = (labels[i] > 0.5f);
        const float x  = logits[i];
        const float t  = targets[i];
        const float mv = fmaxf(-x, 0.0f);
        const float sp = __logf(__expf(-mv) + __expf(-x - mv)) + mv;
        bce = (1.0f - t) * x + (1.0f + (pw - 1.0f) * t) * sp;

        if (pos) {
            const int  b   = bin_of(p);
            const int  idx = atomicAdd(&g_pc[b], 1);
            if (idx < CAP) {
                g_pbins[b * CAP + idx] = p;
                atomicAdd(&g_ps[b], p);
            } else {
                const int oi = atomicAdd(&g_povf, 1);
                if (oi < MAXB) g_ovfP[oi] = p;
            }
        } else {
            const float c   = m + p;
            const int   b   = bin_of(c);
            const int   idx = atomicAdd(&g_nc[b], 1);
            if (idx < CAP) {
                g_nbins[b * CAP + idx] = c;
                atomicAdd(&g_ns[b], c);
            } else {
                const int oi = atomicAdd(&g_novf, 1);
                if (oi < MAXB) g_ovfN[oi] = c;
            }
        }
    }

    // n1: one atomic per warp
    const unsigned bp = __ballot_sync(0xffffffffu, pos);
    if (lane == 0 && bp) atomicAdd(&g_n1, __popc(bp));

    // BCE block reduce -> one store per block
    double d = (double)bce;
    #pragma unroll
    for (int off = 16; off; off >>= 1)
        d += __shfl_down_sync(0xffffffffu, d, off);
    __shared__ double wb8[8];
    if (lane == 0) wb8[w] = d;
    __syncthreads();
    if (tid == 0) {
        double s = 0.0;
        #pragma unroll
        for (int k = 0; k < 8; k++) s += wb8[k];
        g_bceB[blockIdx.x] = s;
    }
}

// ---------------------------------------------------------------------------
// Kernel 2: per-block smem suffix scan; per-pos closed form (LDS);
// distributed same-bin crosses; tiny last-block finalize + reset.
// ---------------------------------------------------------------------------
__global__ void __launch_bounds__(T2)
k2(const float* __restrict__ preds, const float* __restrict__ labels,
   int n, int nb1, const void* __restrict__ marginp, float* __restrict__ out)
{
    __shared__ double ssufS[NBIN + 1];
    __shared__ int    ssufC[NBIN + 1];
    __shared__ double tS[T2];
    __shared__ int    tC[T2];

    const int tid  = threadIdx.x;
    const int lane = tid & 31, w = tid >> 5;
    const int bid  = blockIdx.x;
    const int g    = gridDim.x;
    const float m  = read_margin(marginp);

    // ---- suffix scan of stored-neg bins (parallel, per block) -------------
    double v[BPT]; int c4[BPT];
    #pragma unroll
    for (int k = 0; k < BPT; k++) {
        const int b = BPT * tid + k;
        c4[k] = min(g_nc[b], CAP);
        v[k]  = (double)g_ns[b];
    }
    double Tt = 0.0; int Ct = 0;
    #pragma unroll
    for (int k = 0; k < BPT; k++) { Tt += v[k]; Ct += c4[k]; }
    tS[tid] = Tt; tC[tid] = Ct;
    __syncthreads();
    for (int off = 1; off < T2; off <<= 1) {
        double aS = 0.0; int aC = 0;
        if (tid + off < T2) { aS = tS[tid + off]; aC = tC[tid + off]; }
        __syncthreads();
        tS[tid] += aS; tC[tid] += aC;
        __syncthreads();
    }
    double accS = tS[tid] - Tt;             // suffix strictly after my bins
    int    accC = tC[tid] - Ct;
    #pragma unroll
    for (int k = BPT - 1; k >= 0; k--) {
        const int b = BPT * tid + k;
        ssufS[b + 1] = accS;
        ssufC[b + 1] = accC;
        accS += v[k]; accC += c4[k];
    }
    __syncthreads();                        // (index 0 never read)

    double acc = 0.0;

    // ---- per-element closed form (LDS suffix reads) -----------------------
    const int i = bid * T2 + tid;
    if (i < n && labels[i] > 0.5f) {
        const float a  = preds[i];
        const int   ka = bin_of(a);
        acc += ssufS[ka + 1] - (double)a * (double)ssufC[ka + 1];
    }

    // ---- same-bin dense crosses: bin b handled by (block b%g, thread b/g) --
    for (int b = tid * g + bid; b < NBIN; b += T2 * g) {   // 1 bin for g=32
        const int cp = min(g_pc[b], CAP);
        const int cn = min(g_nc[b], CAP);
        if (cp && cn) {
            const float* np = &g_nbins[b * CAP];
            const float* pp = &g_pbins[b * CAP];
            float s = 0.f;
            for (int ii = 0; ii < cp; ii++) {
                const float a = pp[ii];
                float t0 = 0.f;
                for (int j = 0; j < cn; j++)
                    t0 += fmaxf(np[j] - a, 0.f);
                s += t0;
            }
            acc += (double)s;
        }
    }

    // ---- overflow exact paths (block 0; empty in practice) ----------------
    if (bid == 0) {
        const int novf = min(g_novf, MAXB);
        for (int t = tid; t < novf; t += T2) {     // ovf-neg x ALL pos
            const float c = g_ovfN[t];
            float s = 0.f;
            for (int j = 0; j < n; j++)
                if (labels[j] > 0.5f) s += fmaxf(c - preds[j], 0.f);
            acc += (double)s;
        }
        const int povf = min(g_povf, MAXB);
        for (int t = tid; t < povf; t += T2) {     // ovf-pos x stored negs
            const float a = g_ovfP[t];
            const int   b = bin_of(a);
            acc += ssufS[b + 1] - (double)a * (double)ssufC[b + 1];
            const int cn = min(g_nc[b], CAP);
            float s = 0.f;
            for (int j = 0; j < cn; j++)
                s += fmaxf(g_nbins[b * CAP + j] - a, 0.f);
            acc += (double)s;
        }
    }

    // ---- block reduce + publish -------------------------------------------
    #pragma unroll
    for (int off = 16; off; off >>= 1)
        acc += __shfl_down_sync(0xffffffffu, acc, off);
    __shared__ double wr8[8];
    if (lane == 0) wr8[w] = acc;
    __syncthreads();
    __shared__ int isLast;
    if (tid == 0) {
        double s = 0.0;
        #pragma unroll
        for (int k = 0; k < 8; k++) s += wr8[k];
        g_mixB[bid] = s;
        __threadfence();
        isLast = (atomicAdd(&g_done2, 1u) == (unsigned)g - 1u) ? 1 : 0;
    }
    __syncthreads();

    // ---- last block: TINY finalize + parallel state reset -----------------
    if (isLast) {
        if (w == 0) {                       // one warp: 32+32 partials
            double fm = (lane < g)   ? __ldcg(&g_mixB[lane]) : 0.0;
            double fb = (lane < nb1) ? __ldcg(&g_bceB[lane]) : 0.0;
            #pragma unroll
            for (int off = 16; off; off >>= 1) {
                fm += __shfl_down_sync(0xffffffffu, fm, off);
                fb += __shfl_down_sync(0xffffffffu, fb, off);
            }
            if (lane == 0) {
                const int    n1  = g_n1;
                const double dn1 = (double)n1, dn0 = (double)(n - n1);
                const double eqPairs = 0.5 * (dn1 * (dn1 - 1.0) + dn0 * (dn0 - 1.0));
                const double mm = (m > 0.0f) ? (double)m : 0.0;
                out[0] = (float)((mm * eqPairs + fm) / (double)n);
                out[1] = (float)(fb / (double)n);
            }
        }
        // parallel reset for next graph replay
        for (int j = tid; j < NBIN; j += T2) {
            g_nc[j] = 0; g_ns[j] = 0.f;
            g_pc[j] = 0; g_ps[j] = 0.f;
        }
        if (tid == 0) { g_novf = 0; g_povf = 0; g_n1 = 0; g_done2 = 0u; }
    }
}

// ---------------------------------------------------------------------------
extern "C" void kernel_launch(void* const* d_in, const int* in_sizes, int n_in,
                              void* d_out, int out_size)
{
    const float* preds   = (const float*)d_in[0];
    const float* labels  = (const float*)d_in[1];
    const float* logits  = (const float*)d_in[2];
    const float* targets = (const float*)d_in[3];
    const float* pw      = (const float*)d_in[4];
    const void*  marginp = (n_in >= 6) ? d_in[5] : nullptr;
    const int n = in_sizes[0];
    float* out = (float*)d_out;

    const int g = min((n + T1 - 1) / T1, GMAX);    // 32 for B=8192
    k1<<<g, T1>>>(preds, labels, logits, targets, pw, n, marginp);
    k2<<<g, T2>>>(preds, labels, n, g, marginp, out);
}

// round 16
// speedup vs baseline: 2.5679x; 2.0134x over previous
#include <cuda_runtime.h>
#include <math.h>

// ----------------------------------------------------------------------------
// Brute force at 2 instr/pair. B=8192, labels in {0,1}.
//   equal-label pairs: relu(m) each -> closed form from n1
//   mixed pairs: relu(c - a), c = m + p_neg, a = p_pos
//                = max(c, a) - a   ->  FMNMX + FADD per pair, -cnt*a per chain
// k1: BCE partials + warp-ballot compaction into g_pos / g_negm (c stored).
// k2: 2 x 74 blocks; 8 pos/thread in regs (index-clamped, invalid chains
//     zeroed exactly), neg slice in smem (pad -1e30 -> max()=a -> cancels
//     exactly against cnt*a). Last block: tiny finalize + reset.
// ----------------------------------------------------------------------------

#define T1    256
#define G1MAX 64
#define T2    256
#define PX    2
#define NY    74
#define RG    8                  // pos per thread (PX*T2*RG = 4096 per sweep)
#define MAXB  8192
#define TILE  120                // > ceil(8192/74)=111, mult of 4

// scratch (allocation-free rule: __device__ globals)
__device__ float    g_pos[MAXB];
__device__ float    g_negm[MAXB];          // m + p_neg
__device__ int      g_posCnt = 0;
__device__ int      g_negCnt = 0;
__device__ double   g_bceB[G1MAX];
__device__ double   g_mixB[PX * NY];
__device__ unsigned g_done = 0;

__device__ __forceinline__ float read_margin(const void* p) {
    if (p == nullptr) return 1.0f;
    int v = *(const int*)p;
    if (v >= -1000000 && v <= 1000000) return (float)v;   // int scalar
    return __int_as_float(v);                             // float bits
}

// ---------------------------------------------------------------------------
// Kernel 1: BCE partials + compaction (proven ~2.7us shape from R3).
// ---------------------------------------------------------------------------
__global__ void __launch_bounds__(T1)
k1(const float* __restrict__ preds,  const float* __restrict__ labels,
   const float* __restrict__ logits, const float* __restrict__ targets,
   const float* __restrict__ pw_, int n, const void* __restrict__ marginp)
{
    const int tid  = threadIdx.x;
    const int lane = tid & 31, w = tid >> 5;
    const int i    = blockIdx.x * T1 + tid;
    const float m  = read_margin(marginp);
    const float pw = pw_[0];

    float p = 0.f, bce = 0.f;
    bool pos = false;
    const bool inb = (i < n);
    if (inb) {
        p   = preds[i];
        pos = (labels[i] > 0.5f);
        const float x  = logits[i];
        const float t  = targets[i];
        const float mv = fmaxf(-x, 0.0f);
        const float sp = __logf(__expf(-mv) + __expf(-x - mv)) + mv;
        bce = (1.0f - t) * x + (1.0f + (pw - 1.0f) * t) * sp;
    }

    // warp compaction + per-warp segment reservation (order-free; sums commute)
    const unsigned bm   = __ballot_sync(0xffffffffu, pos && inb);
    const unsigned vm   = __ballot_sync(0xffffffffu, inb);
    const int      rank = __popc(bm & ((1u << lane) - 1u));
    const int      c    = __popc(bm);
    const int      v    = __popc(vm);
    int bp = 0, bn = 0;
    if (lane == 0) {
        bp = atomicAdd(&g_posCnt, c);
        bn = atomicAdd(&g_negCnt, v - c);
    }
    bp = __shfl_sync(0xffffffffu, bp, 0);
    bn = __shfl_sync(0xffffffffu, bn, 0);
    if (inb) {
        if (pos) g_pos[bp + rank] = p;
        else     g_negm[bn + (__popc(vm & ((1u << lane) - 1u)) - rank)] = m + p;
    }

    // BCE block reduce -> one plain store per block
    double d = (double)bce;
    #pragma unroll
    for (int off = 16; off; off >>= 1)
        d += __shfl_down_sync(0xffffffffu, d, off);
    __shared__ double wb8[8];
    if (lane == 0) wb8[w] = d;
    __syncthreads();
    if (tid == 0) {
        double s = 0.0;
        #pragma unroll
        for (int k = 0; k < 8; k++) s += wb8[k];
        g_bceB[blockIdx.x] = s;
    }
}

// ---------------------------------------------------------------------------
// Kernel 2: pair sum at 2 instr/pair via max-trick.
// ---------------------------------------------------------------------------
__global__ void __launch_bounds__(T2)
k2(int n, int nb1, const void* __restrict__ marginp, float* __restrict__ out)
{
    const int tid  = threadIdx.x;
    const int lane = tid & 31, w = tid >> 5;
    const int bx   = blockIdx.x, by = blockIdx.y;
    const int bid  = by * PX + bx;
    const float m  = read_margin(marginp);

    const int n1 = g_posCnt;
    const int n0 = n - n1;

    // ---- neg slice -> smem (c already includes margin), pad -1e30 ---------
    const int nchunk = (n0 + NY - 1) / NY;
    const int ns   = by * nchunk;
    const int cnt  = max(min(ns + nchunk, n0) - ns, 0);
    const int cnt4 = (cnt + 3) & ~3;
    __shared__ __align__(16) float tile[TILE];
    for (int i = tid; i < cnt4; i += T2)
        tile[i] = (i < cnt) ? g_negm[ns + i] : -1e30f;   // max(-1e30,a)=a -> cancels
    __syncthreads();

    double acc = 0.0;
    const float fcnt = (float)cnt4;

    // ---- pos sweep: RG chains in registers, grid-stride over chunks -------
    for (int pb = bx * (T2 * RG); pb < n1; pb += PX * T2 * RG) {
        float a[RG]; bool val[RG]; float s[RG];
        #pragma unroll
        for (int k = 0; k < RG; k++) {
            const int idx = pb + k * T2 + tid;
            val[k] = (idx < n1);
            a[k]   = g_pos[min(idx, n1 - 1)];     // clamped; zeroed later
            s[k]   = 0.f;
        }
        for (int j = 0; j < cnt4; j += 4) {
            const float4 t = *(const float4*)&tile[j];
            #pragma unroll
            for (int k = 0; k < RG; k++) {
                s[k] += fmaxf(t.x, a[k]);
                s[k] += fmaxf(t.y, a[k]);
                s[k] += fmaxf(t.z, a[k]);
                s[k] += fmaxf(t.w, a[k]);
            }
        }
        #pragma unroll
        for (int k = 0; k < RG; k++) {
            const float r = s[k] - fcnt * a[k];   // Σ max(c,a) - cnt*a = Σ relu(c-a)
            acc += val[k] ? (double)r : 0.0;
        }
    }

    // ---- block reduce + publish -------------------------------------------
    #pragma unroll
    for (int off = 16; off; off >>= 1)
        acc += __shfl_down_sync(0xffffffffu, acc, off);
    __shared__ double wr8[8];
    if (lane == 0) wr8[w] = acc;
    __syncthreads();
    __shared__ int isLast;
    if (tid == 0) {
        double s = 0.0;
        #pragma unroll
        for (int k = 0; k < 8; k++) s += wr8[k];
        g_mixB[bid] = s;
        __threadfence();
        isLast = (atomicAdd(&g_done, 1u) == (unsigned)(PX * NY) - 1u) ? 1 : 0;
    }
    __syncthreads();

    // ---- last block: TINY finalize + reset --------------------------------
    if (isLast) {
        double fm = 0.0, fb = 0.0;
        for (int j = tid; j < PX * NY; j += T2) fm += __ldcg(&g_mixB[j]);
        for (int j = tid; j < nb1; j += T2)     fb += __ldcg(&g_bceB[j]);
        #pragma unroll
        for (int off = 16; off; off >>= 1) {
            fm += __shfl_down_sync(0xffffffffu, fm, off);
            fb += __shfl_down_sync(0xffffffffu, fb, off);
        }
        __shared__ double zm[8], zb[8];
        if (lane == 0) { zm[w] = fm; zb[w] = fb; }
        __syncthreads();
        if (tid == 0) {
            double sm = 0.0, sb = 0.0;
            #pragma unroll
            for (int k = 0; k < 8; k++) { sm += zm[k]; sb += zb[k]; }
            const double dn1 = (double)n1, dn0 = (double)n0;
            const double eqPairs = 0.5 * (dn1 * (dn1 - 1.0) + dn0 * (dn0 - 1.0));
            const double mm = (m > 0.0f) ? (double)m : 0.0;
            out[0] = (float)((mm * eqPairs + sm) / (double)n);
            out[1] = (float)(sb / (double)n);
            g_posCnt = 0; g_negCnt = 0; g_done = 0u;   // reset for next replay
        }
    }
}

// ---------------------------------------------------------------------------
extern "C" void kernel_launch(void* const* d_in, const int* in_sizes, int n_in,
                              void* d_out, int out_size)
{
    const float* preds   = (const float*)d_in[0];
    const float* labels  = (const float*)d_in[1];
    const float* logits  = (const float*)d_in[2];
    const float* targets = (const float*)d_in[3];
    const float* pw      = (const float*)d_in[4];
    const void*  marginp = (n_in >= 6) ? d_in[5] : nullptr;
    const int n = in_sizes[0];
    float* out = (float*)d_out;

    const int g1 = min((n + T1 - 1) / T1, G1MAX);
    k1<<<g1, T1>>>(preds, labels, logits, targets, pw, n, marginp);
    k2<<<dim3(PX, NY), T2>>>(n, g1, marginp, out);
}